// round 2
// baseline (speedup 1.0000x reference)
#include <cuda_runtime.h>
#include <math.h>
#include <stdint.h>

// ---------------- scratch (device globals; no allocation allowed) ----------
__device__ double g_sum[768];
__device__ double g_sumsq[768];
__device__ float  g_scale[768];
__device__ float  g_shift[768];
__device__ float  g_W0p[512 * 3 * 768];   // packed layer0 weights [j][g][d], g in {i,g,o}
__device__ float  g_W1p[512 * 3 * 512];   // packed layer1 weights
__device__ float  g_gc0[512 * 3];         // per-gate constants layer0 (shift-GEMV + biases)
__device__ float  g_gc1[512 * 3];         // per-gate constants layer1 (biases)
__device__ float  g_h1in[(size_t)65536 * 512];  // layer0 output / layer1 input
__device__ float  g_h2  [(size_t)65536 * 512];  // layer1 output (h)

// ---------------- BN stats ----------------
__global__ void zero_stats_kernel() {
    int i = threadIdx.x;
    g_sum[i] = 0.0; g_sumsq[i] = 0.0;
}

__global__ void stats_kernel(const float* __restrict__ x, int rowsPerBlock, int nrows) {
    int c = threadIdx.x;                       // 768 threads: one per feature
    long r0 = (long)blockIdx.x * rowsPerBlock;
    float s = 0.f, s2 = 0.f;
    for (int r = 0; r < rowsPerBlock; ++r) {
        long row = r0 + r;
        if (row < nrows) {
            float v = x[row * 768 + c];
            s += v; s2 += v * v;
        }
    }
    atomicAdd(&g_sum[c], (double)s);
    atomicAdd(&g_sumsq[c], (double)s2);
}

__global__ void prep_kernel(const float* __restrict__ gamma,
                            const float* __restrict__ beta, int nrows) {
    int c = threadIdx.x;
    double mean = g_sum[c] / (double)nrows;
    double var  = g_sumsq[c] / (double)nrows - mean * mean;
    float sc = gamma[c] * (float)(1.0 / sqrt(var + 1e-5));
    g_scale[c] = sc;
    g_shift[c] = beta[c] - (float)mean * sc;
}

// ---------------- weight repack: [dir][4H][K] -> [j(512)][g(3: i,g,o)][K] ----
__global__ void repack0_kernel(const float* __restrict__ w) {
    int idx = blockIdx.x * blockDim.x + threadIdx.x;
    if (idx >= 512 * 3 * 768) return;
    int d  = idx % 768;
    int jg = idx / 768;
    int g  = jg % 3;
    int j  = jg / 3;
    int dir = j >> 8, jj = j & 255;
    int grow = (g == 0) ? jj : (g == 1 ? 512 + jj : 768 + jj);   // i / g / o rows
    g_W0p[idx] = w[((size_t)(dir * 1024 + grow)) * 768 + d];
}

__global__ void repack1_kernel(const float* __restrict__ w) {
    int idx = blockIdx.x * blockDim.x + threadIdx.x;
    if (idx >= 512 * 3 * 512) return;
    int d  = idx % 512;
    int jg = idx / 512;
    int g  = jg % 3;
    int j  = jg / 3;
    int dir = j >> 8, jj = j & 255;
    int grow = (g == 0) ? jj : (g == 1 ? 512 + jj : 768 + jj);
    g_W1p[idx] = w[((size_t)(dir * 1024 + grow)) * 512 + d];
}

// gc0[jg] = dot(shift, W0_row) + b_ih + b_hh    (one warp per output)
__global__ void gconst0_kernel(const float* __restrict__ w,
                               const float* __restrict__ bih,
                               const float* __restrict__ bhh) {
    int warpId = (blockIdx.x * blockDim.x + threadIdx.x) >> 5;
    int lane = threadIdx.x & 31;
    if (warpId >= 1536) return;
    int g = warpId % 3, j = warpId / 3;
    int dir = j >> 8, jj = j & 255;
    int grow = (g == 0) ? jj : (g == 1 ? 512 + jj : 768 + jj);
    const float* wr = w + (size_t)(dir * 1024 + grow) * 768;
    float s = 0.f;
    for (int k = lane; k < 768; k += 32) s += g_shift[k] * wr[k];
    #pragma unroll
    for (int o = 16; o; o >>= 1) s += __shfl_down_sync(0xffffffffu, s, o);
    if (!lane) g_gc0[warpId] = s + bih[dir * 1024 + grow] + bhh[dir * 1024 + grow];
}

__global__ void gconst1_kernel(const float* __restrict__ bih,
                               const float* __restrict__ bhh) {
    int jg = blockIdx.x * blockDim.x + threadIdx.x;
    if (jg >= 1536) return;
    int g = jg % 3, j = jg / 3;
    int dir = j >> 8, jj = j & 255;
    int grow = (g == 0) ? jj : (g == 1 ? 512 + jj : 768 + jj);
    g_gc1[jg] = bih[dir * 1024 + grow] + bhh[dir * 1024 + grow];
}

// ---------------- fused GEMM + LSTM activation ------------------------------
// Out[n, j] = sigmoid(o)*tanh(sigmoid(i)*tanh(g)) where {i,g,o} = A[n,:] . Wp[j][{0,1,2}][:] + gc
// Block tile: 64 rows x 64 h-cols (each h-col = 3 dot products). 256 threads, 4x4 per thread.
template <bool LAYER0>
__global__ __launch_bounds__(256)
void gemm_lstm_kernel(const float* __restrict__ xin) {
    constexpr int K = LAYER0 ? 768 : 512;
    const float* __restrict__ A  = LAYER0 ? xin : g_h1in;
    const float* __restrict__ Wp = LAYER0 ? g_W0p : g_W1p;
    const float* __restrict__ gc = LAYER0 ? g_gc0 : g_gc1;
    float* __restrict__ out      = LAYER0 ? g_h1in : g_h2;

    __shared__ __align__(16) float As[16][64];
    __shared__ __align__(16) float Bs[16][192];

    int tid = threadIdx.x;
    int tr = tid >> 4;          // 0..15  -> rows tr*4..tr*4+3
    int tc = tid & 15;          // 0..15  -> h-cols tc*4..tc*4+3

    int a_m  = tid >> 2;        // 0..63
    int a_k4 = (tid & 3) << 2;  // 0,4,8,12
    const float* Arow = A + ((size_t)blockIdx.x * 64 + a_m) * K + a_k4;
    const float* Brow = Wp + ((size_t)blockIdx.y * 192 + tid) * K;  // valid if tid<192

    float acc[4][4][3];
    #pragma unroll
    for (int r = 0; r < 4; r++)
        #pragma unroll
        for (int c = 0; c < 4; c++)
            { acc[r][c][0] = 0.f; acc[r][c][1] = 0.f; acc[r][c][2] = 0.f; }

    for (int kt = 0; kt < K; kt += 16) {
        float4 av = *(const float4*)(Arow + kt);
        if (LAYER0) {
            av.x *= g_scale[kt + a_k4 + 0];
            av.y *= g_scale[kt + a_k4 + 1];
            av.z *= g_scale[kt + a_k4 + 2];
            av.w *= g_scale[kt + a_k4 + 3];
        }
        As[a_k4 + 0][a_m] = av.x;
        As[a_k4 + 1][a_m] = av.y;
        As[a_k4 + 2][a_m] = av.z;
        As[a_k4 + 3][a_m] = av.w;
        if (tid < 192) {
            float4 b0 = *(const float4*)(Brow + kt + 0);
            float4 b1 = *(const float4*)(Brow + kt + 4);
            float4 b2 = *(const float4*)(Brow + kt + 8);
            float4 b3 = *(const float4*)(Brow + kt + 12);
            Bs[ 0][tid] = b0.x; Bs[ 1][tid] = b0.y; Bs[ 2][tid] = b0.z; Bs[ 3][tid] = b0.w;
            Bs[ 4][tid] = b1.x; Bs[ 5][tid] = b1.y; Bs[ 6][tid] = b1.z; Bs[ 7][tid] = b1.w;
            Bs[ 8][tid] = b2.x; Bs[ 9][tid] = b2.y; Bs[10][tid] = b2.z; Bs[11][tid] = b2.w;
            Bs[12][tid] = b3.x; Bs[13][tid] = b3.y; Bs[14][tid] = b3.z; Bs[15][tid] = b3.w;
        }
        __syncthreads();

        #pragma unroll
        for (int k = 0; k < 16; k++) {
            const float4 a4 = *(const float4*)(&As[k][tr << 2]);
            float ar[4] = {a4.x, a4.y, a4.z, a4.w};
            const float4 p = *(const float4*)(&Bs[k][tc * 12 + 0]);
            const float4 q = *(const float4*)(&Bs[k][tc * 12 + 4]);
            const float4 s = *(const float4*)(&Bs[k][tc * 12 + 8]);
            float br[12] = {p.x, p.y, p.z, p.w, q.x, q.y, q.z, q.w, s.x, s.y, s.z, s.w};
            #pragma unroll
            for (int r = 0; r < 4; r++)
                #pragma unroll
                for (int c = 0; c < 4; c++) {
                    acc[r][c][0] += ar[r] * br[c * 3 + 0];
                    acc[r][c][1] += ar[r] * br[c * 3 + 1];
                    acc[r][c][2] += ar[r] * br[c * 3 + 2];
                }
        }
        __syncthreads();
    }

    int row0 = blockIdx.x * 64 + (tr << 2);
    int col0 = blockIdx.y * 64 + (tc << 2);
    #pragma unroll
    for (int r = 0; r < 4; r++)
        #pragma unroll
        for (int c = 0; c < 4; c++) {
            int jg3 = (col0 + c) * 3;
            float iv = acc[r][c][0] + gc[jg3 + 0];
            float gv = acc[r][c][1] + gc[jg3 + 1];
            float ov = acc[r][c][2] + gc[jg3 + 2];
            float cv = (1.f / (1.f + expf(-iv))) * tanhf(gv);
            float hv = (1.f / (1.f + expf(-ov))) * tanhf(cv);
            out[(size_t)(row0 + r) * 512 + col0 + c] = hv;
        }
}

// ---------------- FC: e[n,k] = h[n,:] . fc_w[k,:] + fc_b[k] -----------------
__global__ __launch_bounds__(256)
void fc_kernel(const float* __restrict__ fcw, const float* __restrict__ fcb,
               float* __restrict__ e, int nrows) {
    __shared__ float w0[512], w1[512];
    for (int i = threadIdx.x; i < 512; i += blockDim.x) {
        w0[i] = fcw[i];
        w1[i] = fcw[512 + i];
    }
    __syncthreads();
    int warp = (int)((blockIdx.x * (size_t)blockDim.x + threadIdx.x) >> 5);
    int lane = threadIdx.x & 31;
    if (warp >= nrows) return;
    const float* h = g_h2 + (size_t)warp * 512;
    float s0 = 0.f, s1 = 0.f;
    #pragma unroll
    for (int k = lane * 4; k < 512; k += 128) {
        float4 hv = *(const float4*)(h + k);
        s0 += hv.x * w0[k] + hv.y * w0[k + 1] + hv.z * w0[k + 2] + hv.w * w0[k + 3];
        s1 += hv.x * w1[k] + hv.y * w1[k + 1] + hv.z * w1[k + 2] + hv.w * w1[k + 3];
    }
    #pragma unroll
    for (int o = 16; o; o >>= 1) {
        s0 += __shfl_down_sync(0xffffffffu, s0, o);
        s1 += __shfl_down_sync(0xffffffffu, s1, o);
    }
    if (!lane) {
        e[(size_t)warp * 2 + 0] = s0 + fcb[0];
        e[(size_t)warp * 2 + 1] = s1 + fcb[1];
    }
}

// ---------------- CRF NLL (log-semiring parallel reduce, doubles) -----------
__device__ __forceinline__ double lse2(double a, double b) {
    double m = fmax(a, b), n = fmin(a, b);
    return m + log1p(exp(n - m));
}

__global__ __launch_bounds__(1024)
void crf_kernel(const float* __restrict__ e, const int* __restrict__ tags,
                const float* __restrict__ startv, const float* __restrict__ endv,
                const float* __restrict__ trans, float* __restrict__ loss_out, int N) {
    __shared__ double sP[1024][4];
    __shared__ double sNum[1024];
    int tid = threadIdx.x;
    const double T00 = trans[0], T01 = trans[1], T10 = trans[2], T11 = trans[3];
    const double NEG = -1e30;

    int chunk = (N + 1023) >> 10;
    long s0 = (long)tid * chunk;
    long s1 = s0 + chunk; if (s1 > N) s1 = N;

    double P00 = 0.0, P01 = NEG, P10 = NEG, P11 = 0.0;  // identity
    double np = 0.0;
    for (long n = s0; n < s1; ++n) {
        int t = tags[n];
        np += (double)e[n * 2 + t];
        if (n >= 1) {
            int tp = tags[n - 1];
            np += (tp == 0) ? (t == 0 ? T00 : T01) : (t == 0 ? T10 : T11);
            double e0 = (double)e[n * 2 + 0];
            double e1 = (double)e[n * 2 + 1];
            double n00 = lse2(P00 + T00, P01 + T10) + e0;
            double n01 = lse2(P00 + T01, P01 + T11) + e1;
            double n10 = lse2(P10 + T00, P11 + T10) + e0;
            double n11 = lse2(P10 + T01, P11 + T11) + e1;
            P00 = n00; P01 = n01; P10 = n10; P11 = n11;
        }
    }
    sP[tid][0] = P00; sP[tid][1] = P01; sP[tid][2] = P10; sP[tid][3] = P11;
    sNum[tid] = np;
    __syncthreads();

    // adjacent-pair tree reduce (order-preserving: A (earlier) x B (later))
    for (int nthr = 1024; nthr > 1; nthr >>= 1) {
        int half = nthr >> 1;
        double a0, a1, a2, a3, b0, b1, b2, b3, nn;
        bool act = tid < half;
        if (act) {
            a0 = sP[2 * tid][0];     a1 = sP[2 * tid][1];
            a2 = sP[2 * tid][2];     a3 = sP[2 * tid][3];
            b0 = sP[2 * tid + 1][0]; b1 = sP[2 * tid + 1][1];
            b2 = sP[2 * tid + 1][2]; b3 = sP[2 * tid + 1][3];
            nn = sNum[2 * tid] + sNum[2 * tid + 1];
        }
        __syncthreads();
        if (act) {
            sP[tid][0] = lse2(a0 + b0, a1 + b2);
            sP[tid][1] = lse2(a0 + b1, a1 + b3);
            sP[tid][2] = lse2(a2 + b0, a3 + b2);
            sP[tid][3] = lse2(a2 + b1, a3 + b3);
            sNum[tid] = nn;
        }
        __syncthreads();
    }

    if (tid == 0) {
        double num = sNum[0] + (double)startv[tags[0]] + (double)endv[tags[N - 1]];
        double a0 = (double)startv[0] + (double)e[0];
        double a1 = (double)startv[1] + (double)e[1];
        double f0 = lse2(a0 + sP[0][0], a1 + sP[0][2]);
        double f1 = lse2(a0 + sP[0][1], a1 + sP[0][3]);
        double den = lse2(f0 + (double)endv[0], f1 + (double)endv[1]);
        loss_out[0] = (float)(den - num);   // -(num - den)
    }
}

// ---------------- launch ----------------
extern "C" void kernel_launch(void* const* d_in, const int* in_sizes, int n_in,
                              void* d_out, int out_size) {
    const float* x        = (const float*)d_in[0];
    const float* gamma    = (const float*)d_in[1];
    const float* beta     = (const float*)d_in[2];
    const float* w_ih_l0  = (const float*)d_in[3];
    // d_in[4] = w_hh_l0 (unused: h0 = 0)
    const float* b_ih_l0  = (const float*)d_in[5];
    const float* b_hh_l0  = (const float*)d_in[6];
    const float* w_ih_l1  = (const float*)d_in[7];
    // d_in[8] = w_hh_l1 (unused)
    const float* b_ih_l1  = (const float*)d_in[9];
    const float* b_hh_l1  = (const float*)d_in[10];
    const float* fc_w     = (const float*)d_in[11];
    const float* fc_b     = (const float*)d_in[12];
    const float* crf_start= (const float*)d_in[13];
    const float* crf_end  = (const float*)d_in[14];
    const float* crf_trans= (const float*)d_in[15];
    const int*   labels   = (const int*)d_in[16];

    int N = in_sizes[0] / 768;      // 65536
    float* out = (float*)d_out;
    float* e = out + 1;             // logits region: (loss, logits) flattened

    // BN stats
    zero_stats_kernel<<<1, 768>>>();
    int rpb = 512;
    int nblk = (N + rpb - 1) / rpb;
    stats_kernel<<<nblk, 768>>>(x, rpb, N);
    prep_kernel<<<1, 768>>>(gamma, beta, N);

    // weight repack + gate constants
    repack0_kernel<<<(512 * 3 * 768 + 255) / 256, 256>>>(w_ih_l0);
    repack1_kernel<<<(512 * 3 * 512 + 255) / 256, 256>>>(w_ih_l1);
    gconst0_kernel<<<(1536 * 32 + 255) / 256, 256>>>(w_ih_l0, b_ih_l0, b_hh_l0);
    gconst1_kernel<<<(1536 + 255) / 256, 256>>>(b_ih_l1, b_hh_l1);

    // fused GEMM + LSTM activation, both layers
    dim3 grid(N / 64, 8);
    gemm_lstm_kernel<true><<<grid, 256>>>(x);
    gemm_lstm_kernel<false><<<grid, 256>>>(x);

    // FC -> logits (written straight into d_out)
    fc_kernel<<<(N / 8), 256>>>(fc_w, fc_b, e, N);

    // CRF NLL -> loss at d_out[0]
    crf_kernel<<<1, 1024>>>(e, labels, crf_start, crf_end, crf_trans, out, N);
}

// round 3
// speedup vs baseline: 1.7549x; 1.7549x over previous
#include <cuda_runtime.h>
#include <cuda_bf16.h>
#include <math.h>
#include <stdint.h>

#define NROWS 65536

// ---------------- scratch (device globals; no allocation allowed) ----------
__device__ double g_sum[768];
__device__ double g_sumsq[768];
__device__ float  g_scale[768];
__device__ float  g_shift[768];
__device__ __nv_bfloat16 g_xh[(size_t)NROWS * 768];
__device__ __nv_bfloat16 g_xl[(size_t)NROWS * 768];
__device__ __nv_bfloat16 g_W0h[1536 * 768];
__device__ __nv_bfloat16 g_W0l[1536 * 768];
__device__ __nv_bfloat16 g_W1h[1536 * 512];
__device__ __nv_bfloat16 g_W1l[1536 * 512];
__device__ __nv_bfloat16 g_h1h[(size_t)NROWS * 512];
__device__ __nv_bfloat16 g_h1l[(size_t)NROWS * 512];
__device__ float g_h2[(size_t)NROWS * 512];
__device__ float g_gc0[1536];
__device__ float g_gc1[1536];

// ---------------- BN stats ----------------
__global__ void zero_stats_kernel() {
    int i = threadIdx.x;
    g_sum[i] = 0.0; g_sumsq[i] = 0.0;
}

__global__ void stats_kernel(const float* __restrict__ x, int rowsPerBlock, int nrows) {
    int c = threadIdx.x;                       // 768 threads: one per feature
    long r0 = (long)blockIdx.x * rowsPerBlock;
    float s = 0.f, s2 = 0.f;
    for (int r = 0; r < rowsPerBlock; ++r) {
        long row = r0 + r;
        if (row < nrows) {
            float v = x[row * 768 + c];
            s += v; s2 += v * v;
        }
    }
    atomicAdd(&g_sum[c], (double)s);
    atomicAdd(&g_sumsq[c], (double)s2);
}

__global__ void prep_kernel(const float* __restrict__ gamma,
                            const float* __restrict__ beta, int nrows) {
    int c = threadIdx.x;
    double mean = g_sum[c] / (double)nrows;
    double var  = g_sumsq[c] / (double)nrows - mean * mean;
    float sc = gamma[c] * (float)(1.0 / sqrt(var + 1e-5));
    g_scale[c] = sc;
    g_shift[c] = beta[c] - (float)mean * sc;
}

// ---------------- split x*scale into bf16 hi/lo -----------------------------
__global__ void split_x_kernel(const float4* __restrict__ x4) {
    size_t i = (size_t)blockIdx.x * blockDim.x + threadIdx.x;   // over NROWS*768/4
    float4 v = x4[i];
    int c = (int)(i % 192) * 4;
    v.x *= g_scale[c + 0]; v.y *= g_scale[c + 1];
    v.z *= g_scale[c + 2]; v.w *= g_scale[c + 3];
    __nv_bfloat16 h0 = __float2bfloat16(v.x);
    __nv_bfloat16 h1 = __float2bfloat16(v.y);
    __nv_bfloat16 h2 = __float2bfloat16(v.z);
    __nv_bfloat16 h3 = __float2bfloat16(v.w);
    __nv_bfloat16 l0 = __float2bfloat16(v.x - __bfloat162float(h0));
    __nv_bfloat16 l1 = __float2bfloat16(v.y - __bfloat162float(h1));
    __nv_bfloat16 l2 = __float2bfloat16(v.z - __bfloat162float(h2));
    __nv_bfloat16 l3 = __float2bfloat16(v.w - __bfloat162float(h3));
    __nv_bfloat162* ph = (__nv_bfloat162*)g_xh;
    __nv_bfloat162* pl = (__nv_bfloat162*)g_xl;
    ph[i * 2 + 0] = __halves2bfloat162(h0, h1);
    ph[i * 2 + 1] = __halves2bfloat162(h2, h3);
    pl[i * 2 + 0] = __halves2bfloat162(l0, l1);
    pl[i * 2 + 1] = __halves2bfloat162(l2, l3);
}

// ---------------- weight repack: rows n = j*3+g (g in {i,g,o}), hi/lo split --
template <int K, bool L0>
__global__ void repackW_kernel(const float* __restrict__ w) {
    __nv_bfloat16* wh = L0 ? g_W0h : g_W1h;
    __nv_bfloat16* wl = L0 ? g_W0l : g_W1l;
    int idx = blockIdx.x * blockDim.x + threadIdx.x;
    if (idx >= 1536 * K) return;
    int d = idx % K;
    int n = idx / K;
    int g = n % 3, j = n / 3;
    int dir = j >> 8, jj = j & 255;
    int grow = (g == 0) ? jj : (g == 1 ? 512 + jj : 768 + jj);   // i / g / o rows
    float v = w[(size_t)(dir * 1024 + grow) * K + d];
    __nv_bfloat16 h = __float2bfloat16(v);
    wh[idx] = h;
    wl[idx] = __float2bfloat16(v - __bfloat162float(h));
}

// gc0[n] = dot(shift, W0_row) + b_ih + b_hh    (one warp per output)
__global__ void gconst0_kernel(const float* __restrict__ w,
                               const float* __restrict__ bih,
                               const float* __restrict__ bhh) {
    int warpId = (blockIdx.x * blockDim.x + threadIdx.x) >> 5;
    int lane = threadIdx.x & 31;
    if (warpId >= 1536) return;
    int g = warpId % 3, j = warpId / 3;
    int dir = j >> 8, jj = j & 255;
    int grow = (g == 0) ? jj : (g == 1 ? 512 + jj : 768 + jj);
    const float* wr = w + (size_t)(dir * 1024 + grow) * 768;
    float s = 0.f;
    for (int k = lane; k < 768; k += 32) s += g_shift[k] * wr[k];
    #pragma unroll
    for (int o = 16; o; o >>= 1) s += __shfl_down_sync(0xffffffffu, s, o);
    if (!lane) g_gc0[warpId] = s + bih[dir * 1024 + grow] + bhh[dir * 1024 + grow];
}

__global__ void gconst1_kernel(const float* __restrict__ bih,
                               const float* __restrict__ bhh) {
    int n = blockIdx.x * blockDim.x + threadIdx.x;
    if (n >= 1536) return;
    int g = n % 3, j = n / 3;
    int dir = j >> 8, jj = j & 255;
    int grow = (g == 0) ? jj : (g == 1 ? 512 + jj : 768 + jj);
    g_gc1[n] = bih[dir * 1024 + grow] + bhh[dir * 1024 + grow];
}

// ---------------- tensor-core GEMM + fused LSTM epilogue --------------------
// C[128 x 96] per CTA. bf16x3 split: acc += Ah*Bh + Ah*Bl + Al*Bh (fp32 accum).
// 8 warps: 2 (M) x 4 (N), warp tile 64 x 24 (4 m16 tiles x 3 n8 blocks).

__device__ __forceinline__ void ldsm4(uint32_t& r0, uint32_t& r1, uint32_t& r2,
                                      uint32_t& r3, uint32_t addr) {
    asm volatile("ldmatrix.sync.aligned.m8n8.x4.shared.b16 {%0,%1,%2,%3}, [%4];"
                 : "=r"(r0), "=r"(r1), "=r"(r2), "=r"(r3) : "r"(addr));
}
__device__ __forceinline__ void ldsm2(uint32_t& r0, uint32_t& r1, uint32_t addr) {
    asm volatile("ldmatrix.sync.aligned.m8n8.x2.shared.b16 {%0,%1}, [%2];"
                 : "=r"(r0), "=r"(r1) : "r"(addr));
}
__device__ __forceinline__ void mma16816(float* c, const uint32_t* a, const uint32_t* b) {
    asm volatile("mma.sync.aligned.m16n8k16.row.col.f32.bf16.bf16.f32 "
                 "{%0,%1,%2,%3}, {%4,%5,%6,%7}, {%8,%9}, {%0,%1,%2,%3};"
                 : "+f"(c[0]), "+f"(c[1]), "+f"(c[2]), "+f"(c[3])
                 : "r"(a[0]), "r"(a[1]), "r"(a[2]), "r"(a[3]), "r"(b[0]), "r"(b[1]));
}
__device__ __forceinline__ void cpasync16(uint32_t dst, const void* src) {
    asm volatile("cp.async.cg.shared.global [%0], [%1], 16;" :: "r"(dst), "l"(src));
}

// smem layout per buffer (bf16, row stride 40 elems = 80B, conflict-free LDSM):
//   Ah: 128x40 (10240B)  Al: +10240  Bh: +20480 (96x40=7680B)  Bl: +28160
// buffer size 35840B, double buffered = 71680B. Epilogue reuses as float[128][100].
#define GBUF   35840
#define OFF_AL 10240
#define OFF_BH 20480
#define OFF_BL 28160

template <bool L0>
__global__ void __launch_bounds__(256) gemm_lstm_tc() {
    constexpr int K = L0 ? 768 : 512;
    constexpr int NCH = K / 32;
    const __nv_bfloat16* __restrict__ Ah = L0 ? g_xh : g_h1h;
    const __nv_bfloat16* __restrict__ Al = L0 ? g_xl : g_h1l;
    const __nv_bfloat16* __restrict__ Bh = L0 ? g_W0h : g_W1h;
    const __nv_bfloat16* __restrict__ Bl = L0 ? g_W0l : g_W1l;
    const float* __restrict__ gc = L0 ? g_gc0 : g_gc1;

    extern __shared__ char smem[];
    uint32_t sbase = (uint32_t)__cvta_generic_to_shared(smem);

    const int tid = threadIdx.x;
    const int m0 = blockIdx.y * 128;
    const int n0 = blockIdx.x * 96;     // N-fastest grid: A strips shared via L2

    // -------- async load lambda: one 32-wide K chunk into buffer b ----------
    auto issue = [&](int kt, int b) {
        uint32_t sA = sbase + b * GBUF;
        #pragma unroll
        for (int it = 0; it < 2; ++it) {
            int idx = tid + it * 256;
            int r = idx >> 2, q = idx & 3;
            uint32_t d = sA + r * 80 + q * 16;
            const size_t go = (size_t)(m0 + r) * K + kt + q * 8;
            cpasync16(d, Ah + go);
            cpasync16(d + OFF_AL, Al + go);
        }
        {
            int r = tid >> 2, q = tid & 3;
            uint32_t d = sA + OFF_BH + r * 80 + q * 16;
            const size_t go = (size_t)(n0 + r) * K + kt + q * 8;
            cpasync16(d, Bh + go);
            cpasync16(d + (OFF_BL - OFF_BH), Bl + go);
            if (tid < 128) {
                int r2 = 64 + (tid >> 2), q2 = tid & 3;
                uint32_t d2 = sA + OFF_BH + r2 * 80 + q2 * 16;
                const size_t go2 = (size_t)(n0 + r2) * K + kt + q2 * 8;
                cpasync16(d2, Bh + go2);
                cpasync16(d2 + (OFF_BL - OFF_BH), Bl + go2);
            }
        }
        asm volatile("cp.async.commit_group;");
    };

    const int lane = tid & 31, wid = tid >> 5;
    const int wm = (wid & 1) * 64;
    const int wn = (wid >> 1) * 24;

    // ldmatrix per-lane selectors
    const int msel   = lane >> 3;
    const int arow_f = (msel & 1) * 8 + (lane & 7);
    const int akoff  = (msel >> 1) * 8;
    const int brow_f = (msel >> 1) * 8 + (lane & 7);
    const int bkoff  = (msel & 1) * 8;
    const int l2     = lane & 15;
    const int b2row  = 16 + (l2 & 7);
    const int b2koff = ((l2 >> 3) & 1) * 8;

    float acc[4][3][4];
    #pragma unroll
    for (int mt = 0; mt < 4; mt++)
        #pragma unroll
        for (int nb = 0; nb < 3; nb++)
            #pragma unroll
            for (int r = 0; r < 4; r++) acc[mt][nb][r] = 0.f;

    issue(0, 0);

    #pragma unroll 1
    for (int c = 0; c < NCH; ++c) {
        if (c + 1 < NCH) {
            issue((c + 1) * 32, (c + 1) & 1);
            asm volatile("cp.async.wait_group 1;");
        } else {
            asm volatile("cp.async.wait_group 0;");
        }
        __syncthreads();
        uint32_t sA = sbase + (c & 1) * GBUF;

        #pragma unroll
        for (int ks = 0; ks < 32; ks += 16) {
            uint32_t ah[4][4], al[4][4], bh[3][2], bl[3][2];
            #pragma unroll
            for (int mt = 0; mt < 4; mt++) {
                uint32_t ad = sA + (wm + mt * 16 + arow_f) * 80 + (ks + akoff) * 2;
                ldsm4(ah[mt][0], ah[mt][1], ah[mt][2], ah[mt][3], ad);
                ldsm4(al[mt][0], al[mt][1], al[mt][2], al[mt][3], ad + OFF_AL);
            }
            {
                uint32_t bd = sA + OFF_BH + (wn + brow_f) * 80 + (ks + bkoff) * 2;
                ldsm4(bh[0][0], bh[0][1], bh[1][0], bh[1][1], bd);
                ldsm4(bl[0][0], bl[0][1], bl[1][0], bl[1][1], bd + (OFF_BL - OFF_BH));
                uint32_t bd2 = sA + OFF_BH + (wn + b2row) * 80 + (ks + b2koff) * 2;
                ldsm2(bh[2][0], bh[2][1], bd2);
                ldsm2(bl[2][0], bl[2][1], bd2 + (OFF_BL - OFF_BH));
            }
            #pragma unroll
            for (int mt = 0; mt < 4; mt++)
                #pragma unroll
                for (int nb = 0; nb < 3; nb++) {
                    mma16816(acc[mt][nb], ah[mt], bh[nb]);
                    mma16816(acc[mt][nb], ah[mt], bl[nb]);
                    mma16816(acc[mt][nb], al[mt], bh[nb]);
                }
        }
        __syncthreads();
    }

    // -------- fused epilogue: stage accum to smem, recombine gate triples ---
    float* sC = (float*)smem;
    #pragma unroll
    for (int mt = 0; mt < 4; mt++)
        #pragma unroll
        for (int nb = 0; nb < 3; nb++) {
            int r = wm + mt * 16 + (lane >> 2);
            int cc = wn + nb * 8 + (lane & 3) * 2;
            sC[r * 100 + cc]           = acc[mt][nb][0];
            sC[r * 100 + cc + 1]       = acc[mt][nb][1];
            sC[(r + 8) * 100 + cc]     = acc[mt][nb][2];
            sC[(r + 8) * 100 + cc + 1] = acc[mt][nb][3];
        }
    __syncthreads();

    #pragma unroll
    for (int t = 0; t < 16; t++) {
        int idx = t * 256 + tid;
        int r = idx >> 5, j = idx & 31;
        float iv = sC[r * 100 + 3 * j + 0] + gc[n0 + 3 * j + 0];
        float gv = sC[r * 100 + 3 * j + 1] + gc[n0 + 3 * j + 1];
        float ov = sC[r * 100 + 3 * j + 2] + gc[n0 + 3 * j + 2];
        float cv = (1.f / (1.f + expf(-iv))) * tanhf(gv);
        float hv = (1.f / (1.f + expf(-ov))) * tanhf(cv);
        size_t o = (size_t)(m0 + r) * 512 + (size_t)(n0 / 3 + j);
        if (L0) {
            __nv_bfloat16 hh = __float2bfloat16(hv);
            g_h1h[o] = hh;
            g_h1l[o] = __float2bfloat16(hv - __bfloat162float(hh));
        } else {
            g_h2[o] = hv;
        }
    }
}

// ---------------- FC: e[n,k] = h[n,:] . fc_w[k,:] + fc_b[k] -----------------
__global__ __launch_bounds__(256)
void fc_kernel(const float* __restrict__ fcw, const float* __restrict__ fcb,
               float* __restrict__ e, int nrows) {
    __shared__ float w0[512], w1[512];
    for (int i = threadIdx.x; i < 512; i += blockDim.x) {
        w0[i] = fcw[i];
        w1[i] = fcw[512 + i];
    }
    __syncthreads();
    int warp = (int)((blockIdx.x * (size_t)blockDim.x + threadIdx.x) >> 5);
    int lane = threadIdx.x & 31;
    if (warp >= nrows) return;
    const float* h = g_h2 + (size_t)warp * 512;
    float s0 = 0.f, s1 = 0.f;
    #pragma unroll
    for (int k = lane * 4; k < 512; k += 128) {
        float4 hv = *(const float4*)(h + k);
        s0 += hv.x * w0[k] + hv.y * w0[k + 1] + hv.z * w0[k + 2] + hv.w * w0[k + 3];
        s1 += hv.x * w1[k] + hv.y * w1[k + 1] + hv.z * w1[k + 2] + hv.w * w1[k + 3];
    }
    #pragma unroll
    for (int o = 16; o; o >>= 1) {
        s0 += __shfl_down_sync(0xffffffffu, s0, o);
        s1 += __shfl_down_sync(0xffffffffu, s1, o);
    }
    if (!lane) {
        e[(size_t)warp * 2 + 0] = s0 + fcb[0];
        e[(size_t)warp * 2 + 1] = s1 + fcb[1];
    }
}

// ---------------- CRF NLL (log-semiring parallel reduce, doubles) -----------
__device__ __forceinline__ double lse2(double a, double b) {
    double m = fmax(a, b), n = fmin(a, b);
    return m + log1p(exp(n - m));
}

__global__ __launch_bounds__(1024)
void crf_kernel(const float* __restrict__ e, const int* __restrict__ tags,
                const float* __restrict__ startv, const float* __restrict__ endv,
                const float* __restrict__ trans, float* __restrict__ loss_out, int N) {
    __shared__ double sP[1024][4];
    __shared__ double sNum[1024];
    int tid = threadIdx.x;
    const double T00 = trans[0], T01 = trans[1], T10 = trans[2], T11 = trans[3];
    const double NEG = -1e30;

    int chunk = (N + 1023) >> 10;
    long s0 = (long)tid * chunk;
    long s1 = s0 + chunk; if (s1 > N) s1 = N;

    double P00 = 0.0, P01 = NEG, P10 = NEG, P11 = 0.0;  // identity
    double np = 0.0;
    for (long n = s0; n < s1; ++n) {
        int t = tags[n];
        np += (double)e[n * 2 + t];
        if (n >= 1) {
            int tp = tags[n - 1];
            np += (tp == 0) ? (t == 0 ? T00 : T01) : (t == 0 ? T10 : T11);
            double e0 = (double)e[n * 2 + 0];
            double e1 = (double)e[n * 2 + 1];
            double n00 = lse2(P00 + T00, P01 + T10) + e0;
            double n01 = lse2(P00 + T01, P01 + T11) + e1;
            double n10 = lse2(P10 + T00, P11 + T10) + e0;
            double n11 = lse2(P10 + T01, P11 + T11) + e1;
            P00 = n00; P01 = n01; P10 = n10; P11 = n11;
        }
    }
    sP[tid][0] = P00; sP[tid][1] = P01; sP[tid][2] = P10; sP[tid][3] = P11;
    sNum[tid] = np;
    __syncthreads();

    for (int nthr = 1024; nthr > 1; nthr >>= 1) {
        int half = nthr >> 1;
        double a0, a1, a2, a3, b0, b1, b2, b3, nn;
        bool act = tid < half;
        if (act) {
            a0 = sP[2 * tid][0];     a1 = sP[2 * tid][1];
            a2 = sP[2 * tid][2];     a3 = sP[2 * tid][3];
            b0 = sP[2 * tid + 1][0]; b1 = sP[2 * tid + 1][1];
            b2 = sP[2 * tid + 1][2]; b3 = sP[2 * tid + 1][3];
            nn = sNum[2 * tid] + sNum[2 * tid + 1];
        }
        __syncthreads();
        if (act) {
            sP[tid][0] = lse2(a0 + b0, a1 + b2);
            sP[tid][1] = lse2(a0 + b1, a1 + b3);
            sP[tid][2] = lse2(a2 + b0, a3 + b2);
            sP[tid][3] = lse2(a2 + b1, a3 + b3);
            sNum[tid] = nn;
        }
        __syncthreads();
    }

    if (tid == 0) {
        double num = sNum[0] + (double)startv[tags[0]] + (double)endv[tags[N - 1]];
        double a0 = (double)startv[0] + (double)e[0];
        double a1 = (double)startv[1] + (double)e[1];
        double f0 = lse2(a0 + sP[0][0], a1 + sP[0][2]);
        double f1 = lse2(a0 + sP[0][1], a1 + sP[0][3]);
        double den = lse2(f0 + (double)endv[0], f1 + (double)endv[1]);
        loss_out[0] = (float)(den - num);   // -(num - den)
    }
}

// ---------------- launch ----------------
extern "C" void kernel_launch(void* const* d_in, const int* in_sizes, int n_in,
                              void* d_out, int out_size) {
    const float* x        = (const float*)d_in[0];
    const float* gamma    = (const float*)d_in[1];
    const float* beta     = (const float*)d_in[2];
    const float* w_ih_l0  = (const float*)d_in[3];
    const float* b_ih_l0  = (const float*)d_in[5];
    const float* b_hh_l0  = (const float*)d_in[6];
    const float* w_ih_l1  = (const float*)d_in[7];
    const float* b_ih_l1  = (const float*)d_in[9];
    const float* b_hh_l1  = (const float*)d_in[10];
    const float* fc_w     = (const float*)d_in[11];
    const float* fc_b     = (const float*)d_in[12];
    const float* crf_start= (const float*)d_in[13];
    const float* crf_end  = (const float*)d_in[14];
    const float* crf_trans= (const float*)d_in[15];
    const int*   labels   = (const int*)d_in[16];

    int N = in_sizes[0] / 768;      // 65536
    float* out = (float*)d_out;
    float* e = out + 1;             // (loss, logits) flattened

    cudaFuncSetAttribute((const void*)gemm_lstm_tc<true>,
                         cudaFuncAttributeMaxDynamicSharedMemorySize, 2 * GBUF);
    cudaFuncSetAttribute((const void*)gemm_lstm_tc<false>,
                         cudaFuncAttributeMaxDynamicSharedMemorySize, 2 * GBUF);

    // BN stats
    zero_stats_kernel<<<1, 768>>>();
    int rpb = 512;
    int nblk = (N + rpb - 1) / rpb;
    stats_kernel<<<nblk, 768>>>(x, rpb, N);
    prep_kernel<<<1, 768>>>(gamma, beta, N);

    // x*scale -> bf16 hi/lo
    split_x_kernel<<<(N * 768 / 4 + 255) / 256, 256>>>((const float4*)x);

    // weights -> packed bf16 hi/lo + gate constants
    repackW_kernel<768, true ><<<(1536 * 768 + 255) / 256, 256>>>(w_ih_l0);
    repackW_kernel<512, false><<<(1536 * 512 + 255) / 256, 256>>>(w_ih_l1);
    gconst0_kernel<<<(1536 * 32 + 255) / 256, 256>>>(w_ih_l0, b_ih_l0, b_hh_l0);
    gconst1_kernel<<<(1536 + 255) / 256, 256>>>(b_ih_l1, b_hh_l1);

    // tensor-core GEMM + fused LSTM activation (grid: N-tiles fastest for L2 reuse)
    dim3 gg(16, N / 128);
    gemm_lstm_tc<true ><<<gg, 256, 2 * GBUF>>>();
    gemm_lstm_tc<false><<<gg, 256, 2 * GBUF>>>();

    // FC -> logits
    fc_kernel<<<(N / 8), 256>>>(fc_w, fc_b, e, N);

    // CRF NLL -> loss
    crf_kernel<<<1, 1024>>>(e, labels, crf_start, crf_end, crf_trans, out, N);
}